// round 10
// baseline (speedup 1.0000x reference)
#include <cuda_runtime.h>
#include <cuda_bf16.h>
#include <math.h>
#include <float.h>
#include <stdint.h>

// Problem constants (fixed by the benchmark's setup_inputs)
#define BDIM 8192
#define EDIM 256
#define CDIM 25
#define CAP  4096
#define KP1MAX 64

// ---------------- device scratch (static, allocation-free) ----------------
__device__ float g_sq[BDIM];
__device__ int   g_cnt[BDIM];
__device__ float g_cval[(size_t)BDIM * CAP];
__device__ int   g_cidx[(size_t)BDIM * CAP];
__device__ int   g_labels[BDIM];
__device__ float g_stats[4];                          // meanSq, varSq, vbar
__device__ __nv_bfloat16 g_hi[(size_t)BDIM * EDIM];   // bf16 high part
__device__ __nv_bfloat16 g_lo[(size_t)BDIM * EDIM];   // bf16 residual

// ---------------- warp-level bf16 HMMA ----------------
__device__ __forceinline__ void mma_bf16(float* c, const uint32_t* a, const uint32_t* b) {
    asm volatile(
        "mma.sync.aligned.m16n8k16.row.col.f32.bf16.bf16.f32 "
        "{%0,%1,%2,%3}, {%4,%5,%6,%7}, {%8,%9}, {%0,%1,%2,%3};\n"
        : "+f"(c[0]), "+f"(c[1]), "+f"(c[2]), "+f"(c[3])
        : "r"(a[0]), "r"(a[1]), "r"(a[2]), "r"(a[3]), "r"(b[0]), "r"(b[1]));
}

__device__ __forceinline__ void ldsm4(uint32_t* r, uint32_t addr) {
    asm volatile(
        "ldmatrix.sync.aligned.m8n8.x4.shared.b16 {%0,%1,%2,%3}, [%4];"
        : "=r"(r[0]), "=r"(r[1]), "=r"(r[2]), "=r"(r[3]) : "r"(addr));
}

__device__ __forceinline__ void cp16(uint32_t dst, const void* src) {
    asm volatile("cp.async.cg.shared.global [%0], [%1], 16;" :: "r"(dst), "l"(src));
}
#define CP_COMMIT() asm volatile("cp.async.commit_group;" ::: "memory")
#define CP_WAIT(n)  asm volatile("cp.async.wait_group %0;" :: "n"(n) : "memory")

// ---------------- 0: zero counts + labels ----------------
__global__ void k_pre(const float* __restrict__ cat) {
    int i = blockIdx.x * blockDim.x + threadIdx.x;
    if (i < BDIM) {
        g_cnt[i] = 0;
        const float* r = cat + (size_t)i * CDIM;
        float best = r[0];
        int bi = 0;
#pragma unroll
        for (int c = 1; c < CDIM; c++) {
            float v = r[c];
            if (v > best) { best = v; bi = c; }
        }
        g_labels[i] = bi;
    }
}

// ---------------- 1: fused convert (fp32 -> bf16 hi/lo) + row norms ----------
__global__ void k_cvt_norm(const float* __restrict__ A) {
    int w = blockIdx.x * 8 + (threadIdx.x >> 5);
    int lane = threadIdx.x & 31;
    const float2* r = (const float2*)(A + (size_t)w * EDIM);
    __nv_bfloat162* hi = (__nv_bfloat162*)(g_hi + (size_t)w * EDIM);
    __nv_bfloat162* lo = (__nv_bfloat162*)(g_lo + (size_t)w * EDIM);
    float s = 0.0f;
#pragma unroll
    for (int e = 0; e < 4; e++) {
        int p = lane + e * 32;
        float2 v = r[p];
        s += v.x * v.x + v.y * v.y;
        __nv_bfloat16 h0 = __float2bfloat16_rn(v.x);
        __nv_bfloat16 h1 = __float2bfloat16_rn(v.y);
        __nv_bfloat16 l0 = __float2bfloat16_rn(v.x - __bfloat162float(h0));
        __nv_bfloat16 l1 = __float2bfloat16_rn(v.y - __bfloat162float(h1));
        hi[p] = __halves2bfloat162(h0, h1);
        lo[p] = __halves2bfloat162(l0, l1);
    }
#pragma unroll
    for (int o = 16; o; o >>= 1) s += __shfl_xor_sync(0xffffffffu, s, o);
    if (lane == 0) g_sq[w] = s;
}

// ---------------- 2: global stats over g_sq ----------------
__global__ void k_stats() {
    __shared__ float r1[256], r2[256];
    int t = threadIdx.x;
    float s = 0.0f, s2 = 0.0f;
    for (int i = t; i < BDIM; i += 256) {
        float v = g_sq[i];
        s += v; s2 += v * v;
    }
    r1[t] = s; r2[t] = s2;
    __syncthreads();
    for (int o = 128; o; o >>= 1) {
        if (t < o) { r1[t] += r1[t + o]; r2[t] += r2[t + o]; }
        __syncthreads();
    }
    if (t == 0) {
        float meanSq = r1[0] / (float)BDIM;
        float varSq = fmaxf(r2[0] / (float)BDIM - meanSq * meanSq, 0.0f);
        g_stats[0] = meanSq;
        g_stats[1] = varSq;
        g_stats[2] = meanSq / (float)EDIM;   // vbar (mean vector ~ 0)
    }
}

// ---------------- 3: HMMA GEMM: KC=32, 2-stage cp.async, LDSM fragments ------
// 128x128 tile per CTA, 16 warps (4x4), warp tile 32x32, 2 CTA/SM.
#define KC 32
#define NCHUNK (EDIM / KC)             // 8
#define RSTRIDE 80                     // bytes per smem row (32 bf16 + 16B pad)
#define TILEB (128 * RSTRIDE)          // 10240 B per tile
#define BUFB (4 * TILEB)               // 40960 B per stage
#define OFF_SQI (2 * BUFB)
#define OFF_T0I (2 * BUFB + 512)
#define OFF_SQJ (2 * BUFB + 1024)
#define OFF_T0J (2 * BUFB + 1536)
#define SMEM_SZ (2 * BUFB + 2048)      // 83968 B -> 2 CTAs/SM

__global__ void __launch_bounds__(512, 2) k_gemm_hmma() {
    extern __shared__ __align__(16) char smem[];
    const int tid = threadIdx.x;
    const int wid = tid >> 5, lane = tid & 31;
    const int wm = wid >> 2, wn = wid & 3;     // warp grid 4 (m) x 4 (n)
    const int g = lane >> 2, q = lane & 3;

    int l = blockIdx.x;
    int bi = (int)((sqrtf(8.0f * (float)l + 1.0f) - 1.0f) * 0.5f);
    while ((bi + 1) * (bi + 2) / 2 <= l) ++bi;
    while (bi * (bi + 1) / 2 > l) --bi;
    int bj = l - bi * (bi + 1) / 2;   // bi >= bj

    // stage per-row sq and cutoff t0 = sq + C1 - 2*sqrt(C2 + C4*sq)
    if (tid < 128) {
        float C1 = g_stats[0], C2 = g_stats[1], C4 = 4.0f * g_stats[2];
        float sqi = g_sq[bi * 128 + tid];
        float sqj = g_sq[bj * 128 + tid];
        ((float*)(smem + OFF_SQI))[tid] = sqi;
        ((float*)(smem + OFF_T0I))[tid] = sqi + C1 - 2.0f * sqrtf(fmaxf(C2 + C4 * sqi, 0.0f));
        ((float*)(smem + OFF_SQJ))[tid] = sqj;
        ((float*)(smem + OFF_T0J))[tid] = sqj + C1 - 2.0f * sqrtf(fmaxf(C2 + C4 * sqj, 0.0f));
    }

    float acc[2][4][4];
#pragma unroll
    for (int mt = 0; mt < 2; mt++)
#pragma unroll
        for (int nt = 0; nt < 4; nt++)
#pragma unroll
            for (int e = 0; e < 4; e++) acc[mt][nt][e] = 0.0f;

    const uint32_t sbase = __cvta_generic_to_shared(smem);

    // cp.async load geometry: 1 uint4 per tile per thread
    const int rr = tid >> 2, c4 = tid & 3;
    const uint32_t so = rr * RSTRIDE + c4 * 16;
    const size_t rowA = (size_t)(bi * 128 + rr) * (EDIM / 8);
    const size_t rowB = (size_t)(bj * 128 + rr) * (EDIM / 8);

    auto load_chunk = [&](int c, int buf) {
        uint32_t sb = sbase + buf * BUFB;
        size_t gA = rowA + c * 4 + c4;
        size_t gB = rowB + c * 4 + c4;
        cp16(sb + 0 * TILEB + so, ((const uint4*)g_hi) + gA);
        cp16(sb + 1 * TILEB + so, ((const uint4*)g_lo) + gA);
        cp16(sb + 2 * TILEB + so, ((const uint4*)g_hi) + gB);
        cp16(sb + 3 * TILEB + so, ((const uint4*)g_lo) + gB);
        CP_COMMIT();
    };

    // ldmatrix per-lane base offsets (within a tile)
    // A x4: matrix idx = lane>>3: {rows+0 k0, rows+8 k0, rows+0 k16B, rows+8 k16B}
    const uint32_t aoff =
        (uint32_t)((wm * 32 + (lane & 7) + ((lane >> 3) & 1) * 8) * RSTRIDE +
                   ((lane >> 4) & 1) * 16);
    // B x4 (covers nt pair): {nt0 k0, nt0 k16B, nt1 k0, nt1 k16B}
    const uint32_t boff =
        (uint32_t)((wn * 32 + (lane & 7) + ((lane >> 4) & 1) * 8) * RSTRIDE +
                   ((lane >> 3) & 1) * 16);

    load_chunk(0, 0);

    for (int c = 0; c < NCHUNK; c++) {
        int buf = c & 1;
        if (c + 1 < NCHUNK) {
            load_chunk(c + 1, buf ^ 1);
            CP_WAIT(1);
        } else {
            CP_WAIT(0);
        }
        __syncthreads();
        const uint32_t sb = sbase + buf * BUFB;
        const uint32_t sAH = sb + 0 * TILEB + aoff;
        const uint32_t sAL = sb + 1 * TILEB + aoff;
        const uint32_t sBH = sb + 2 * TILEB + boff;
        const uint32_t sBL = sb + 3 * TILEB + boff;

        // ---- hi pass: hi*hi + hi*lo ----
#pragma unroll
        for (int ks = 0; ks < 2; ks++) {
            const uint32_t kof = ks * 32;
            uint32_t ah[2][4];
            ldsm4(ah[0], sAH + kof);
            ldsm4(ah[1], sAH + 16 * RSTRIDE + kof);
#pragma unroll
            for (int p = 0; p < 2; p++) {
                uint32_t bh[4], bl[4];
                ldsm4(bh, sBH + p * 16 * RSTRIDE + kof);
                ldsm4(bl, sBL + p * 16 * RSTRIDE + kof);
#pragma unroll
                for (int mt = 0; mt < 2; mt++) {
                    mma_bf16(acc[mt][2 * p + 0], ah[mt], bh + 0);   // hi*hi
                    mma_bf16(acc[mt][2 * p + 1], ah[mt], bh + 2);
                    mma_bf16(acc[mt][2 * p + 0], ah[mt], bl + 0);   // hi*lo
                    mma_bf16(acc[mt][2 * p + 1], ah[mt], bl + 2);
                }
            }
        }
        // ---- lo pass: lo*hi ----
#pragma unroll
        for (int ks = 0; ks < 2; ks++) {
            const uint32_t kof = ks * 32;
            uint32_t al[2][4];
            ldsm4(al[0], sAL + kof);
            ldsm4(al[1], sAL + 16 * RSTRIDE + kof);
#pragma unroll
            for (int p = 0; p < 2; p++) {
                uint32_t bh[4];
                ldsm4(bh, sBH + p * 16 * RSTRIDE + kof);
#pragma unroll
                for (int mt = 0; mt < 2; mt++) {
                    mma_bf16(acc[mt][2 * p + 0], al[mt], bh + 0);   // lo*hi
                    mma_bf16(acc[mt][2 * p + 1], al[mt], bh + 2);
                }
            }
        }
        __syncthreads();   // buffer fully consumed before its next refill
    }

    // epilogue: d^2 = sq_i + sq_j - 2*dot, push candidates below per-row cutoff
    const float* sSQI = (const float*)(smem + OFF_SQI);
    const float* sT0I = (const float*)(smem + OFF_T0I);
    const float* sSQJ = (const float*)(smem + OFF_SQJ);
    const float* sT0J = (const float*)(smem + OFF_T0J);
    bool mir = (bi != bj);
#pragma unroll
    for (int mt = 0; mt < 2; mt++) {
#pragma unroll
        for (int rr2 = 0; rr2 < 2; rr2++) {
            int li = wm * 32 + mt * 16 + g + rr2 * 8;
            int i = bi * 128 + li;
            float sqi = sSQI[li], t0i = sT0I[li];
#pragma unroll
            for (int nt = 0; nt < 4; nt++) {
#pragma unroll
                for (int ee = 0; ee < 2; ee++) {
                    int lj = wn * 32 + nt * 8 + 2 * q + ee;
                    int j = bj * 128 + lj;
                    float d2 = sqi + sSQJ[lj] - 2.0f * acc[mt][nt][rr2 * 2 + ee];
                    if (d2 <= t0i) {
                        int p = atomicAdd(&g_cnt[i], 1);
                        if (p < CAP) {
                            g_cval[(size_t)i * CAP + p] = d2;
                            g_cidx[(size_t)i * CAP + p] = j;
                        }
                    }
                    if (mir && d2 <= sT0J[lj]) {
                        int p = atomicAdd(&g_cnt[j], 1);
                        if (p < CAP) {
                            g_cval[(size_t)j * CAP + p] = d2;
                            g_cidx[(size_t)j * CAP + p] = i;
                        }
                    }
                }
            }
        }
    }
}

// ---------------- 4: per-row selection + entropy ----------------
__global__ void __launch_bounds__(256) k_rows(const float* __restrict__ A,
                                              const int* __restrict__ kptr,
                                              float* __restrict__ outE) {
    __shared__ float sbuf[BDIM];
    __shared__ float svec[EDIM];
    __shared__ float exval[KP1MAX];
    __shared__ int   exidx[KP1MAX];
    __shared__ float swv[8];
    __shared__ int   swi[8];

    int i = blockIdx.x;
    int t = threadIdx.x;
    int kk = kptr ? kptr[0] : 15;
    int KP1 = kk + 1;
    if (KP1 > KP1MAX) KP1 = KP1MAX;
    if (KP1 < 1) KP1 = 1;

    int n = g_cnt[i];
    bool cand = (n >= KP1 && n <= CAP);
    int M;
    int* sidx = (int*)(sbuf + CAP);

    if (cand) {
        M = n;
        for (int p = t; p < n; p += 256) {
            sbuf[p] = g_cval[(size_t)i * CAP + p];
            sidx[p] = g_cidx[(size_t)i * CAP + p];
        }
    } else {
        M = BDIM;
        for (int e = t; e < EDIM; e += 256) svec[e] = A[(size_t)i * EDIM + e];
        __syncthreads();
        float sqi = g_sq[i];
        for (int j = t; j < BDIM; j += 256) {
            const float* rj = A + (size_t)j * EDIM;
            float dot = 0.0f;
#pragma unroll 8
            for (int e = 0; e < EDIM; e++) dot += svec[e] * rj[e];
            sbuf[j] = sqi + g_sq[j] - 2.0f * dot;
        }
    }
    __syncthreads();

    for (int s = 0; s < KP1; s++) {
        float mv = FLT_MAX;
        int mp = 0;
        for (int p = t; p < M; p += 256) {
            float v = sbuf[p];
            if (v < mv) { mv = v; mp = p; }
        }
#pragma unroll
        for (int o = 16; o; o >>= 1) {
            float ov = __shfl_xor_sync(0xffffffffu, mv, o);
            int op = __shfl_xor_sync(0xffffffffu, mp, o);
            if (ov < mv) { mv = ov; mp = op; }
        }
        if ((t & 31) == 0) { swv[t >> 5] = mv; swi[t >> 5] = mp; }
        __syncthreads();
        if (t == 0) {
#pragma unroll
            for (int w = 1; w < 8; w++)
                if (swv[w] < mv) { mv = swv[w]; mp = swi[w]; }
            exval[s] = mv;
            exidx[s] = cand ? sidx[mp] : mp;
            sbuf[mp] = FLT_MAX;
        }
        __syncthreads();
    }

    if (t == 0) {
        float thr = exval[KP1 - 1];
        int cnts[CDIM];
#pragma unroll
        for (int c = 0; c < CDIM; c++) cnts[c] = 0;
        int nn = 0;
        for (int s = 0; s < KP1; s++) {
            if (exval[s] < thr) {
                cnts[g_labels[exidx[s]]]++;
                nn++;
            }
        }
        float inv = (nn > 0) ? (1.0f / (float)nn) : 0.0f;
        float e = 0.0f;
#pragma unroll
        for (int c = 0; c < CDIM; c++) {
            float b = (float)cnts[c] * inv;
            e -= b * logf(b + 1e-5f);
        }
        outE[i] = e;
    }
}

// ---------------- launch ----------------
extern "C" void kernel_launch(void* const* d_in, const int* in_sizes, int n_in,
                              void* d_out, int out_size) {
    const float* enc = (const float*)d_in[0];
    const float* cat = (const float*)d_in[1];
    const int* kptr = (n_in >= 3) ? (const int*)d_in[2] : nullptr;

    float* outEnc = (float*)d_out;
    float* outEnt;
    if (out_size >= BDIM * EDIM + BDIM) {
        outEnt = outEnc + (size_t)BDIM * EDIM;
        cudaMemcpyAsync(outEnc, enc, (size_t)BDIM * EDIM * sizeof(float),
                        cudaMemcpyDeviceToDevice);
    } else {
        outEnt = outEnc;
    }

    cudaFuncSetAttribute(k_gemm_hmma, cudaFuncAttributeMaxDynamicSharedMemorySize, SMEM_SZ);

    k_pre<<<(BDIM + 255) / 256, 256>>>(cat);      // launch 0
    k_cvt_norm<<<BDIM / 8, 256>>>(enc);           // launch 1
    k_stats<<<1, 256>>>();                        // launch 2

    int nb = BDIM / 128;
    int nblocks = nb * (nb + 1) / 2;
    k_gemm_hmma<<<nblocks, 512, SMEM_SZ>>>();     // launch 3  <-- profiled slot

    k_rows<<<BDIM, 256>>>(enc, kptr, outEnt);     // launch 4
}

// round 11
// speedup vs baseline: 1.3270x; 1.3270x over previous
#include <cuda_runtime.h>
#include <cuda_bf16.h>
#include <math.h>
#include <float.h>
#include <stdint.h>

// Problem constants (fixed by the benchmark's setup_inputs)
#define BDIM 8192
#define EDIM 256
#define CDIM 25
#define CAP  4096
#define KP1MAX 64

// ---------------- device scratch (static, allocation-free) ----------------
__device__ float g_sq[BDIM];
__device__ int   g_cnt[BDIM];
__device__ float g_cval[(size_t)BDIM * CAP];
__device__ int   g_cidx[(size_t)BDIM * CAP];
__device__ int   g_labels[BDIM];
__device__ float g_stats[4];                          // meanSq, varSq, vbar
__device__ __nv_bfloat16 g_hi[(size_t)BDIM * EDIM];   // bf16 high part
__device__ __nv_bfloat16 g_lo[(size_t)BDIM * EDIM];   // bf16 residual

// ---------------- warp-level bf16 HMMA ----------------
__device__ __forceinline__ void mma_bf16(float* c, const uint32_t* a, const uint32_t* b) {
    asm volatile(
        "mma.sync.aligned.m16n8k16.row.col.f32.bf16.bf16.f32 "
        "{%0,%1,%2,%3}, {%4,%5,%6,%7}, {%8,%9}, {%0,%1,%2,%3};\n"
        : "+f"(c[0]), "+f"(c[1]), "+f"(c[2]), "+f"(c[3])
        : "r"(a[0]), "r"(a[1]), "r"(a[2]), "r"(a[3]), "r"(b[0]), "r"(b[1]));
}

__device__ __forceinline__ void cp16(uint32_t dst, const void* src) {
    asm volatile("cp.async.cg.shared.global [%0], [%1], 16;" :: "r"(dst), "l"(src));
}
#define CP_COMMIT() asm volatile("cp.async.commit_group;" ::: "memory")
#define CP_WAIT(n)  asm volatile("cp.async.wait_group %0;" :: "n"(n) : "memory")

// ---------------- 0: zero counts + labels ----------------
__global__ void k_pre(const float* __restrict__ cat) {
    int i = blockIdx.x * blockDim.x + threadIdx.x;
    if (i < BDIM) {
        g_cnt[i] = 0;
        const float* r = cat + (size_t)i * CDIM;
        float best = r[0];
        int bi = 0;
#pragma unroll
        for (int c = 1; c < CDIM; c++) {
            float v = r[c];
            if (v > best) { best = v; bi = c; }
        }
        g_labels[i] = bi;
    }
}

// ---------------- 1: fused convert (fp32 -> bf16 hi/lo) + row norms ----------
__global__ void k_cvt_norm(const float* __restrict__ A) {
    int w = blockIdx.x * 8 + (threadIdx.x >> 5);
    int lane = threadIdx.x & 31;
    const float2* r = (const float2*)(A + (size_t)w * EDIM);
    __nv_bfloat162* hi = (__nv_bfloat162*)(g_hi + (size_t)w * EDIM);
    __nv_bfloat162* lo = (__nv_bfloat162*)(g_lo + (size_t)w * EDIM);
    float s = 0.0f;
#pragma unroll
    for (int e = 0; e < 4; e++) {
        int p = lane + e * 32;
        float2 v = r[p];
        s += v.x * v.x + v.y * v.y;
        __nv_bfloat16 h0 = __float2bfloat16_rn(v.x);
        __nv_bfloat16 h1 = __float2bfloat16_rn(v.y);
        __nv_bfloat16 l0 = __float2bfloat16_rn(v.x - __bfloat162float(h0));
        __nv_bfloat16 l1 = __float2bfloat16_rn(v.y - __bfloat162float(h1));
        hi[p] = __halves2bfloat162(h0, h1);
        lo[p] = __halves2bfloat162(l0, l1);
    }
#pragma unroll
    for (int o = 16; o; o >>= 1) s += __shfl_xor_sync(0xffffffffu, s, o);
    if (lane == 0) g_sq[w] = s;
}

// ---------------- 2: global stats over g_sq ----------------
__global__ void k_stats() {
    __shared__ float r1[256], r2[256];
    int t = threadIdx.x;
    float s = 0.0f, s2 = 0.0f;
    for (int i = t; i < BDIM; i += 256) {
        float v = g_sq[i];
        s += v; s2 += v * v;
    }
    r1[t] = s; r2[t] = s2;
    __syncthreads();
    for (int o = 128; o; o >>= 1) {
        if (t < o) { r1[t] += r1[t + o]; r2[t] += r2[t + o]; }
        __syncthreads();
    }
    if (t == 0) {
        float meanSq = r1[0] / (float)BDIM;
        float varSq = fmaxf(r2[0] / (float)BDIM - meanSq * meanSq, 0.0f);
        g_stats[0] = meanSq;
        g_stats[1] = varSq;
        g_stats[2] = meanSq / (float)EDIM;   // vbar (mean vector ~ 0)
    }
}

// ---------------- 3: HMMA GEMM: KC=32, 2-stage cp.async, scalar LDS (R9) -----
// 128x128 tile per CTA, 16 warps (4x4), warp tile 32x32, 2 CTA/SM.
#define KC 32
#define NCHUNK (EDIM / KC)             // 8
#define RSTRIDE 80                     // bytes per smem row (32 bf16 + 16B pad)
#define TILEB (128 * RSTRIDE)          // 10240 B per tile
#define BUFB (4 * TILEB)               // 40960 B per stage
#define OFF_SQI (2 * BUFB)
#define OFF_T0I (2 * BUFB + 512)
#define OFF_SQJ (2 * BUFB + 1024)
#define OFF_T0J (2 * BUFB + 1536)
#define SMEM_SZ (2 * BUFB + 2048)      // 83968 B -> 2 CTAs/SM

__global__ void __launch_bounds__(512, 2) k_gemm_hmma() {
    extern __shared__ __align__(16) char smem[];
    const int tid = threadIdx.x;
    const int wid = tid >> 5, lane = tid & 31;
    const int wm = wid >> 2, wn = wid & 3;     // warp grid 4 (m) x 4 (n)
    const int g = lane >> 2, q = lane & 3;

    int l = blockIdx.x;
    int bi = (int)((sqrtf(8.0f * (float)l + 1.0f) - 1.0f) * 0.5f);
    while ((bi + 1) * (bi + 2) / 2 <= l) ++bi;
    while (bi * (bi + 1) / 2 > l) --bi;
    int bj = l - bi * (bi + 1) / 2;   // bi >= bj

    // stage per-row sq and cutoff t0 = sq + C1 - 2*sqrt(C2 + C4*sq)
    if (tid < 128) {
        float C1 = g_stats[0], C2 = g_stats[1], C4 = 4.0f * g_stats[2];
        float sqi = g_sq[bi * 128 + tid];
        float sqj = g_sq[bj * 128 + tid];
        ((float*)(smem + OFF_SQI))[tid] = sqi;
        ((float*)(smem + OFF_T0I))[tid] = sqi + C1 - 2.0f * sqrtf(fmaxf(C2 + C4 * sqi, 0.0f));
        ((float*)(smem + OFF_SQJ))[tid] = sqj;
        ((float*)(smem + OFF_T0J))[tid] = sqj + C1 - 2.0f * sqrtf(fmaxf(C2 + C4 * sqj, 0.0f));
    }

    float acc[2][4][4];
#pragma unroll
    for (int mt = 0; mt < 2; mt++)
#pragma unroll
        for (int nt = 0; nt < 4; nt++)
#pragma unroll
            for (int e = 0; e < 4; e++) acc[mt][nt][e] = 0.0f;

    const uint32_t sbase = __cvta_generic_to_shared(smem);
    // per-thread load geometry: 1 uint4 per tile (512 thr)
    const int rr = tid >> 2, c4 = tid & 3;
    const uint32_t so = rr * RSTRIDE + c4 * 16;
    const size_t rowA = (size_t)(bi * 128 + rr) * (EDIM / 8);
    const size_t rowB = (size_t)(bj * 128 + rr) * (EDIM / 8);

    auto load_chunk = [&](int c, int buf) {
        uint32_t sb = sbase + buf * BUFB;
        size_t gA = rowA + c * 4 + c4;
        size_t gB = rowB + c * 4 + c4;
        cp16(sb + 0 * TILEB + so, ((const uint4*)g_hi) + gA);
        cp16(sb + 1 * TILEB + so, ((const uint4*)g_lo) + gA);
        cp16(sb + 2 * TILEB + so, ((const uint4*)g_hi) + gB);
        cp16(sb + 3 * TILEB + so, ((const uint4*)g_lo) + gB);
        CP_COMMIT();
    };

    load_chunk(0, 0);

    for (int c = 0; c < NCHUNK; c++) {
        int buf = c & 1;
        if (c + 1 < NCHUNK) {
            load_chunk(c + 1, buf ^ 1);
            CP_WAIT(1);
        } else {
            CP_WAIT(0);
        }
        __syncthreads();
        const char* sb = smem + buf * BUFB;
        const char* sAH = sb + 0 * TILEB;
        const char* sAL = sb + 1 * TILEB;
        const char* sBH = sb + 2 * TILEB;
        const char* sBL = sb + 3 * TILEB;

        // ---- hi pass: hi*hi + hi*lo ----
#pragma unroll
        for (int ks = 0; ks < 2; ks++) {
            const int colb = (ks * 16 + q * 2) * 2;   // byte offset of k pair
            uint32_t af[2][4];
#pragma unroll
            for (int mt = 0; mt < 2; mt++) {
                int row = wm * 32 + mt * 16 + g;
                uint32_t o00 = row * RSTRIDE + colb;
                uint32_t o10 = o00 + 8 * RSTRIDE;
                af[mt][0] = *(const uint32_t*)(sAH + o00);
                af[mt][1] = *(const uint32_t*)(sAH + o10);
                af[mt][2] = *(const uint32_t*)(sAH + o00 + 16);
                af[mt][3] = *(const uint32_t*)(sAH + o10 + 16);
            }
#pragma unroll
            for (int nt = 0; nt < 4; nt++) {
                int rowb = wn * 32 + nt * 8 + g;
                uint32_t ob = rowb * RSTRIDE + colb;
                uint32_t bh[2], bl[2];
                bh[0] = *(const uint32_t*)(sBH + ob);
                bh[1] = *(const uint32_t*)(sBH + ob + 16);
                bl[0] = *(const uint32_t*)(sBL + ob);
                bl[1] = *(const uint32_t*)(sBL + ob + 16);
#pragma unroll
                for (int mt = 0; mt < 2; mt++) {
                    mma_bf16(acc[mt][nt], af[mt], bh);   // hi*hi
                    mma_bf16(acc[mt][nt], af[mt], bl);   // hi*lo
                }
            }
        }
        // ---- lo pass: lo*hi ----
#pragma unroll
        for (int ks = 0; ks < 2; ks++) {
            const int colb = (ks * 16 + q * 2) * 2;
            uint32_t af[2][4];
#pragma unroll
            for (int mt = 0; mt < 2; mt++) {
                int row = wm * 32 + mt * 16 + g;
                uint32_t o00 = row * RSTRIDE + colb;
                uint32_t o10 = o00 + 8 * RSTRIDE;
                af[mt][0] = *(const uint32_t*)(sAL + o00);
                af[mt][1] = *(const uint32_t*)(sAL + o10);
                af[mt][2] = *(const uint32_t*)(sAL + o00 + 16);
                af[mt][3] = *(const uint32_t*)(sAL + o10 + 16);
            }
#pragma unroll
            for (int nt = 0; nt < 4; nt++) {
                int rowb = wn * 32 + nt * 8 + g;
                uint32_t ob = rowb * RSTRIDE + colb;
                uint32_t bh[2];
                bh[0] = *(const uint32_t*)(sBH + ob);
                bh[1] = *(const uint32_t*)(sBH + ob + 16);
#pragma unroll
                for (int mt = 0; mt < 2; mt++)
                    mma_bf16(acc[mt][nt], af[mt], bh);   // lo*hi
            }
        }
        __syncthreads();   // buffer fully consumed before its next refill
    }

    // epilogue: d^2 = sq_i + sq_j - 2*dot, push candidates below per-row cutoff
    const float* sSQI = (const float*)(smem + OFF_SQI);
    const float* sT0I = (const float*)(smem + OFF_T0I);
    const float* sSQJ = (const float*)(smem + OFF_SQJ);
    const float* sT0J = (const float*)(smem + OFF_T0J);
    bool mir = (bi != bj);
#pragma unroll
    for (int mt = 0; mt < 2; mt++) {
#pragma unroll
        for (int rr2 = 0; rr2 < 2; rr2++) {
            int li = wm * 32 + mt * 16 + g + rr2 * 8;
            int i = bi * 128 + li;
            float sqi = sSQI[li], t0i = sT0I[li];
#pragma unroll
            for (int nt = 0; nt < 4; nt++) {
#pragma unroll
                for (int ee = 0; ee < 2; ee++) {
                    int lj = wn * 32 + nt * 8 + 2 * q + ee;
                    int j = bj * 128 + lj;
                    float d2 = sqi + sSQJ[lj] - 2.0f * acc[mt][nt][rr2 * 2 + ee];
                    if (d2 <= t0i) {
                        int p = atomicAdd(&g_cnt[i], 1);
                        if (p < CAP) {
                            g_cval[(size_t)i * CAP + p] = d2;
                            g_cidx[(size_t)i * CAP + p] = j;
                        }
                    }
                    if (mir && d2 <= sT0J[lj]) {
                        int p = atomicAdd(&g_cnt[j], 1);
                        if (p < CAP) {
                            g_cval[(size_t)j * CAP + p] = d2;
                            g_cidx[(size_t)j * CAP + p] = i;
                        }
                    }
                }
            }
        }
    }
}

// ---------------- 4: per-row selection + entropy ----------------
__global__ void __launch_bounds__(256) k_rows(const float* __restrict__ A,
                                              const int* __restrict__ kptr,
                                              float* __restrict__ outE) {
    __shared__ float sbuf[BDIM];
    __shared__ float svec[EDIM];
    __shared__ float exval[KP1MAX];
    __shared__ int   exidx[KP1MAX];
    __shared__ float swv[8];
    __shared__ int   swi[8];
    __shared__ float sthr;
    __shared__ int   hist[CDIM];
    __shared__ int   nncnt;

    int i = blockIdx.x;
    int t = threadIdx.x;
    int kk = kptr ? kptr[0] : 15;
    int KP1 = kk + 1;
    if (KP1 > KP1MAX) KP1 = KP1MAX;
    if (KP1 < 1) KP1 = 1;
    int kth = KP1 - 1;   // 0-indexed rank of the threshold element

    int n = g_cnt[i];
    bool cand = (n >= KP1 && n <= CAP);
    int* sidx = (int*)(sbuf + CAP);

    if (t < CDIM) hist[t] = 0;
    if (t == 0) nncnt = 0;

    if (cand) {
        // ---- fast path: count-based rank selection over n candidates ----
        for (int p = t; p < n; p += 256) {
            sbuf[p] = g_cval[(size_t)i * CAP + p];
            sidx[p] = g_cidx[(size_t)i * CAP + p];
        }
        __syncthreads();

        for (int p = t; p < n; p += 256) {
            float v = sbuf[p];
            int nl = 0, ne = 0;
            for (int j = 0; j < n; j++) {
                float w = sbuf[j];   // broadcast read (uniform address)
                nl += (w < v);
                ne += (w == v);
            }
            if (nl <= kth && kth < nl + ne) sthr = v;   // k-th order statistic
        }
        __syncthreads();
        float thr = sthr;

        for (int p = t; p < n; p += 256) {
            if (sbuf[p] < thr) {
                atomicAdd(&hist[g_labels[sidx[p]]], 1);
                atomicAdd(&nncnt, 1);
            }
        }
        __syncthreads();
    } else {
        // ---- exact fallback: recompute full distance row, serial extraction ----
        int M = BDIM;
        for (int e = t; e < EDIM; e += 256) svec[e] = A[(size_t)i * EDIM + e];
        __syncthreads();
        float sqi = g_sq[i];
        for (int j = t; j < BDIM; j += 256) {
            const float* rj = A + (size_t)j * EDIM;
            float dot = 0.0f;
#pragma unroll 8
            for (int e = 0; e < EDIM; e++) dot += svec[e] * rj[e];
            sbuf[j] = sqi + g_sq[j] - 2.0f * dot;
        }
        __syncthreads();

        for (int s = 0; s < KP1; s++) {
            float mv = FLT_MAX;
            int mp = 0;
            for (int p = t; p < M; p += 256) {
                float v = sbuf[p];
                if (v < mv) { mv = v; mp = p; }
            }
#pragma unroll
            for (int o = 16; o; o >>= 1) {
                float ov = __shfl_xor_sync(0xffffffffu, mv, o);
                int op = __shfl_xor_sync(0xffffffffu, mp, o);
                if (ov < mv) { mv = ov; mp = op; }
            }
            if ((t & 31) == 0) { swv[t >> 5] = mv; swi[t >> 5] = mp; }
            __syncthreads();
            if (t == 0) {
#pragma unroll
                for (int w = 1; w < 8; w++)
                    if (swv[w] < mv) { mv = swv[w]; mp = swi[w]; }
                exval[s] = mv;
                exidx[s] = mp;
                sbuf[mp] = FLT_MAX;
            }
            __syncthreads();
        }
        if (t == 0) {
            float thr = exval[KP1 - 1];
            for (int s = 0; s < KP1; s++) {
                if (exval[s] < thr) {
                    hist[g_labels[exidx[s]]]++;
                    nncnt++;
                }
            }
        }
        __syncthreads();
    }

    if (t == 0) {
        int nn = nncnt;
        float inv = (nn > 0) ? (1.0f / (float)nn) : 0.0f;
        float e = 0.0f;
#pragma unroll
        for (int c = 0; c < CDIM; c++) {
            float b = (float)hist[c] * inv;
            e -= b * logf(b + 1e-5f);
        }
        outE[i] = e;
    }
}

// ---------------- launch ----------------
extern "C" void kernel_launch(void* const* d_in, const int* in_sizes, int n_in,
                              void* d_out, int out_size) {
    const float* enc = (const float*)d_in[0];
    const float* cat = (const float*)d_in[1];
    const int* kptr = (n_in >= 3) ? (const int*)d_in[2] : nullptr;

    float* outEnc = (float*)d_out;
    float* outEnt;
    if (out_size >= BDIM * EDIM + BDIM) {
        outEnt = outEnc + (size_t)BDIM * EDIM;
        cudaMemcpyAsync(outEnc, enc, (size_t)BDIM * EDIM * sizeof(float),
                        cudaMemcpyDeviceToDevice);
    } else {
        outEnt = outEnc;
    }

    cudaFuncSetAttribute(k_gemm_hmma, cudaFuncAttributeMaxDynamicSharedMemorySize, SMEM_SZ);

    k_pre<<<(BDIM + 255) / 256, 256>>>(cat);      // launch 0
    k_cvt_norm<<<BDIM / 8, 256>>>(enc);           // launch 1
    k_stats<<<1, 256>>>();                        // launch 2

    int nb = BDIM / 128;
    int nblocks = nb * (nb + 1) / 2;
    k_gemm_hmma<<<nblocks, 512, SMEM_SZ>>>();     // launch 3  <-- profiled slot

    k_rows<<<BDIM, 256>>>(enc, kptr, outEnt);     // launch 4
}